// round 2
// baseline (speedup 1.0000x reference)
#include <cuda_runtime.h>

#define NROWS 1000000
#define NCOLS 128
#define N_BINS 15

// Scratch (no device allocation allowed): global int histogram + label-dtype flag.
__device__ int g_hist[N_BINS * 2];
__device__ int g_lbl32;  // 1 => labels are int32, 0 => int64

// Kernel 1: zero the histogram and detect label dtype.
// If labels are int64 (little-endian), every odd 32-bit word is a high half == 0
// (values are in [0,128)). If int32, odd words are labels[1],labels[3],... and
// the chance all 64 sampled are zero is (1/128)^64 ~ 0.
__global__ void zero_detect_kernel(const int* __restrict__ labels_raw) {
    int t = threadIdx.x;
    if (t < N_BINS * 2) g_hist[t] = 0;
    if (t == 0) {
        int any = 0;
        #pragma unroll 8
        for (int i = 0; i < 64; i++) any |= labels_raw[2 * i + 1];
        g_lbl32 = (any != 0) ? 1 : 0;
    }
}

// Kernel 2: main pass. One warp per row, grid-stride, prefetch-1.
__global__ __launch_bounds__(512) void conf_acc_kernel(
    const float* __restrict__ logits,
    const void*  __restrict__ labels)
{
    __shared__ int sh[N_BINS * 2];
    if (threadIdx.x < N_BINS * 2) sh[threadIdx.x] = 0;
    __syncthreads();

    const int lane   = threadIdx.x & 31;
    const int warp   = (blockIdx.x * blockDim.x + threadIdx.x) >> 5;
    const int nwarps = (gridDim.x * blockDim.x) >> 5;

    const int        lbl32 = g_lbl32;
    const int*       L32   = (const int*)labels;
    const long long* L64   = (const long long*)labels;

    int r = warp;
    if (r < NROWS) {
        float4 v = ((const float4*)(logits + (size_t)r * NCOLS))[lane];
        for (;;) {
            // Prefetch next row's chunk while we reduce the current one.
            int rn = r + nwarps;
            float4 vn;
            if (rn < NROWS)
                vn = ((const float4*)(logits + (size_t)rn * NCOLS))[lane];

            // ---- per-thread max + first-index over 4 elements ----
            float m  = v.x;
            int  idx = lane * 4;
            if (v.y > m) { m = v.y; idx = lane * 4 + 1; }
            if (v.z > m) { m = v.z; idx = lane * 4 + 2; }
            if (v.w > m) { m = v.w; idx = lane * 4 + 3; }

            // ---- warp xor-butterfly (max, min-index-on-tie) ----
            #pragma unroll
            for (int off = 16; off; off >>= 1) {
                float om = __shfl_xor_sync(0xffffffffu, m,   off);
                int   oi = __shfl_xor_sync(0xffffffffu, idx, off);
                if (om > m || (om == m && oi < idx)) { m = om; idx = oi; }
            }

            // ---- sum of exp(x - m) ----
            float s = __expf(v.x - m) + __expf(v.y - m) +
                      __expf(v.z - m) + __expf(v.w - m);
            #pragma unroll
            for (int off = 16; off; off >>= 1)
                s += __shfl_xor_sync(0xffffffffu, s, off);

            if (lane == 0) {
                float conf = 1.0f / s;                    // max softmax prob
                int b = (int)(conf * 15.0f);              // floor; conf >= 1/128 > 0
                b = b < 0 ? 0 : (b > N_BINS - 1 ? N_BINS - 1 : b);
                int lbl = lbl32 ? L32[r] : (int)L64[r];
                int slot = b * 2 + ((idx == lbl) ? 0 : 1);
                atomicAdd(&sh[slot], 1);
            }

            if (rn >= NROWS) break;
            r = rn;
            v = vn;
        }
    }

    __syncthreads();
    if (threadIdx.x < N_BINS * 2)
        atomicAdd(&g_hist[threadIdx.x], sh[threadIdx.x]);
}

// Kernel 3: convert int counts to float output [N_BINS, 2].
__global__ void finalize_kernel(float* __restrict__ out) {
    int t = threadIdx.x;
    if (t < N_BINS * 2) out[t] = (float)g_hist[t];
}

extern "C" void kernel_launch(void* const* d_in, const int* in_sizes, int n_in,
                              void* d_out, int out_size) {
    const float* logits = (const float*)d_in[0];
    const void*  labels = d_in[1];
    (void)in_sizes; (void)n_in; (void)out_size;

    zero_detect_kernel<<<1, 32>>>((const int*)labels);
    conf_acc_kernel<<<608, 512>>>(logits, labels);
    finalize_kernel<<<1, 32>>>((float*)d_out);
}

// round 4
// speedup vs baseline: 1.9967x; 1.9967x over previous
#include <cuda_runtime.h>

#define NROWS 1000000
#define NCOLS 128
#define N_BINS 15

// Scratch: zero-initialized at module load; finalize_kernel re-zeroes after each
// read, so the all-zero precondition holds for every graph replay.
__device__ int g_hist[N_BINS * 2];

// Main pass: 8 lanes per row, 4 rows per warp per iteration, grid-stride.
__global__ __launch_bounds__(256) void conf_acc_kernel(
    const float* __restrict__ logits,
    const char*  __restrict__ labels)
{
    __shared__ int sh[N_BINS * 2];
    __shared__ int s_shift;

    if (threadIdx.x < N_BINS * 2) sh[threadIdx.x] = 0;
    if (threadIdx.x == 0) {
        // int64 labels (<128) have all-zero high 32-bit words; for int32 the odd
        // words are labels[1,3,..]; P(all 64 zero) for int32 = 128^-64 ~ 0.
        const int* lr = (const int*)labels;
        int any = 0;
        #pragma unroll
        for (int i = 0; i < 64; i++) any |= lr[2 * i + 1];
        s_shift = any ? 2 : 3;            // bytes-per-label shift: int32=4B, int64=8B
    }
    __syncthreads();
    const int shift = s_shift;

    const int lane = threadIdx.x & 31;
    const int sub  = lane & 7;            // lane within 8-lane group
    const int grp  = lane >> 3;           // which of the 4 rows this group owns
    const int warp = (blockIdx.x * blockDim.x + threadIdx.x) >> 5;
    const int nwarp = (gridDim.x * blockDim.x) >> 5;
    const int NQ = NROWS / 4;             // row-quads

    for (int q = warp; q < NQ; q += nwarp) {
        const size_t row = (size_t)q * 4 + grp;
        const float4* rp = (const float4*)(logits + row * NCOLS);

        // 4 independent 16B loads per lane (cols 4sub.., +32, +64, +96)
        float4 a = __ldcs(rp + sub);
        float4 b = __ldcs(rp + sub + 8);
        float4 c = __ldcs(rp + sub + 16);
        float4 d = __ldcs(rp + sub + 24);

        // ---- row max: lane-local tree, then 3-step xor butterfly within group ----
        float m0 = fmaxf(fmaxf(a.x, a.y), fmaxf(a.z, a.w));
        float m1 = fmaxf(fmaxf(b.x, b.y), fmaxf(b.z, b.w));
        float m2 = fmaxf(fmaxf(c.x, c.y), fmaxf(c.z, c.w));
        float m3 = fmaxf(fmaxf(d.x, d.y), fmaxf(d.z, d.w));
        float gm = fmaxf(fmaxf(m0, m1), fmaxf(m2, m3));
        #pragma unroll
        for (int off = 4; off; off >>= 1)
            gm = fmaxf(gm, __shfl_xor_sync(0xffffffffu, gm, off));

        // ---- argmax (first occurrence): lane-local min col, group min-reduce ----
        const int base = sub * 4;
        int col = 0x7fffffff;
        if (d.w == gm) col = base + 99;
        if (d.z == gm) col = base + 98;
        if (d.y == gm) col = base + 97;
        if (d.x == gm) col = base + 96;
        if (c.w == gm) col = base + 67;
        if (c.z == gm) col = base + 66;
        if (c.y == gm) col = base + 65;
        if (c.x == gm) col = base + 64;
        if (b.w == gm) col = base + 35;
        if (b.z == gm) col = base + 34;
        if (b.y == gm) col = base + 33;
        if (b.x == gm) col = base + 32;
        if (a.w == gm) col = base + 3;
        if (a.z == gm) col = base + 2;
        if (a.y == gm) col = base + 1;
        if (a.x == gm) col = base;
        #pragma unroll
        for (int off = 4; off; off >>= 1)
            col = min(col, __shfl_xor_sync(0xffffffffu, col, off));

        // ---- sum exp(x - m): lane-local, group add-reduce ----
        float s = ((__expf(a.x - gm) + __expf(a.y - gm)) +
                   (__expf(a.z - gm) + __expf(a.w - gm))) +
                  ((__expf(b.x - gm) + __expf(b.y - gm)) +
                   (__expf(b.z - gm) + __expf(b.w - gm))) +
                  ((__expf(c.x - gm) + __expf(c.y - gm)) +
                   (__expf(c.z - gm) + __expf(c.w - gm))) +
                  ((__expf(d.x - gm) + __expf(d.y - gm)) +
                   (__expf(d.z - gm) + __expf(d.w - gm)));
        #pragma unroll
        for (int off = 4; off; off >>= 1)
            s += __shfl_xor_sync(0xffffffffu, s, off);

        // ---- group leaders (4 lanes) bin & accumulate in one predicated atomic ----
        if (sub == 0) {
            int lbl = *(const int*)(labels + (row << shift));  // low word works for both dtypes
            float conf = 1.0f / s;                 // max softmax prob, in (0,1]
            int bin = (int)(conf * 15.0f);         // floor; conf > 0
            if (bin > N_BINS - 1) bin = N_BINS - 1;
            atomicAdd(&sh[bin * 2 + ((col == lbl) ? 0 : 1)], 1);
        }
    }

    __syncthreads();
    if (threadIdx.x < N_BINS * 2)
        atomicAdd(&g_hist[threadIdx.x], sh[threadIdx.x]);
}

// Convert counts to float [N_BINS, 2] and reset hist for the next replay.
__global__ void finalize_kernel(float* __restrict__ out) {
    int t = threadIdx.x;
    if (t < N_BINS * 2) {
        out[t] = (float)g_hist[t];
        g_hist[t] = 0;
    }
}

extern "C" void kernel_launch(void* const* d_in, const int* in_sizes, int n_in,
                              void* d_out, int out_size) {
    const float* logits = (const float*)d_in[0];
    const char*  labels = (const char*)d_in[1];
    (void)in_sizes; (void)n_in; (void)out_size;

    conf_acc_kernel<<<1184, 256>>>(logits, labels);
    finalize_kernel<<<1, 32>>>((float*)d_out);
}